// round 15
// baseline (speedup 1.0000x reference)
#include <cuda_runtime.h>
#include <cuda_bf16.h>
#include <stdint.h>

#define N_NODES 100000
#define E_EDGES 1600000
#define DIN 128
#define HID 64
#define DOUT 2

// Scratch (device globals; no allocation allowed). Zero-initialized at load.
// INVARIANT: g_hist is zero at entry to every kernel_launch call.
__device__ int    g_hist[N_NODES];
__device__ int    g_rowstart[N_NODES + 1];
__device__ int    g_cursor[N_NODES];
__device__ int2   g_perm[E_EDGES];                 // {edge, src} sorted by dst
__device__ float  g_hpart[(size_t)N_NODES * HID];  // mean_agg @ W0_bot (pre-bias)
__device__ float  g_h[(size_t)N_NODES * HID];      // hidden activations

__device__ __forceinline__ float4 ldcs4(const float4* p) {
    float4 v;
    asm volatile("ld.global.cs.v4.f32 {%0,%1,%2,%3}, [%4];"
                 : "=f"(v.x), "=f"(v.y), "=f"(v.z), "=f"(v.w) : "l"(p));
    return v;
}

// ---------------- histogram over dst ----------------
__global__ void hist_kernel(const int* __restrict__ ei, int* __restrict__ hist, int E)
{
    int e = blockIdx.x * blockDim.x + threadIdx.x;
    if (e < E) atomicAdd(&hist[ei[E + e]], 1);
}

// ---------------- single-block exclusive scan (consumes + re-zeroes hist) ----------------
__global__ void scan_kernel(int* __restrict__ hist,
                            int* __restrict__ rowstart, int* __restrict__ cursor,
                            int N, int E)
{
    __shared__ int warpsum[32];
    __shared__ int s_carry;
    int tid  = threadIdx.x;
    int lane = tid & 31;
    int wid  = tid >> 5;
    if (tid == 0) s_carry = 0;
    __syncthreads();

    int v = (tid < N) ? hist[tid] : 0;
    for (int base = 0; base < N; base += 1024) {
        int inext = base + 1024 + tid;
        int vnext = (inext < N && base + 1024 < N) ? hist[inext] : 0;

        int incl = v;
        #pragma unroll
        for (int off = 1; off < 32; off <<= 1) {
            int t = __shfl_up_sync(0xFFFFFFFFu, incl, off);
            if (lane >= off) incl += t;
        }
        if (lane == 31) warpsum[wid] = incl;
        __syncthreads();
        if (wid == 0) {
            int w = (lane < 32) ? warpsum[lane] : 0;
            int wi = w;
            #pragma unroll
            for (int off = 1; off < 32; off <<= 1) {
                int t = __shfl_up_sync(0xFFFFFFFFu, wi, off);
                if (lane >= off) wi += t;
            }
            warpsum[lane] = wi - w;
        }
        __syncthreads();
        int carry = s_carry;
        int excl = incl - v + warpsum[wid] + carry;
        int i = base + tid;
        if (i < N) {
            rowstart[i] = excl;
            cursor[i]   = excl;
            hist[i]     = 0;
        }
        __syncthreads();
        if (tid == 1023) s_carry = excl + v;
        __syncthreads();
        v = vnext;
    }
    if (tid == 0) rowstart[N] = E;
}

__global__ void build_kernel(const int* __restrict__ ei, int* __restrict__ cursor,
                             int2* __restrict__ perm, int E)
{
    int e = blockIdx.x * blockDim.x + threadIdx.x;
    if (e >= E) return;
    int s = ei[e];
    int d = ei[E + e];
    int pos = atomicAdd(&cursor[d], 1);
    perm[pos] = make_int2(e, s);
}

// ---------------- fused layer-0 aggregation + W0_bot projection ----------------
// Warp per dst: aggregate 128-ch mean in regs (4-edge batched loads, DRAM-bound),
// then project mean -> 64 ch through W0_bot in the idle FMA/LDS pipes.
// hpart[d] = mean_agg(d) @ W0_bot (pre-bias, pre-relu).
__global__ void __launch_bounds__(256, 6)
agg0proj_kernel(const float* __restrict__ x,
                const float* __restrict__ ea,
                const int2* __restrict__ perm,
                const int* __restrict__ rowstart,
                const float* __restrict__ W0,
                float* __restrict__ hpart,
                int N)
{
    __shared__ float sW0b[DIN * HID];   // 32KB: W0 rows 128..255
    __shared__ float sAcc[8][DIN];      // 4KB: per-warp mean staging

    int tid  = threadIdx.x;
    int lane = tid & 31;
    int wid  = tid >> 5;

    // cooperative stage of W0_bot (contiguous 32KB)
    {
        const float4* w4 = reinterpret_cast<const float4*>(W0 + DIN * HID);
        float4* sw4 = reinterpret_cast<float4*>(sW0b);
        for (int i = tid; i < DIN * HID / 4; i += 256) sw4[i] = w4[i];
    }
    __syncthreads();

    int warp = (blockIdx.x * blockDim.x + tid) >> 5;
    if (warp >= N) return;

    int beg = rowstart[warp];
    int end = rowstart[warp + 1];

    float4 acc = make_float4(0.f, 0.f, 0.f, 0.f);
    for (int base = beg; base < end; base += 32) {
        int take = min(end - base, 32);
        int2 p = make_int2(0, 0);
        if (lane < take) p = perm[base + lane];

        int j = 0;
        for (; j + 4 <= take; j += 4) {
            int e0 = __shfl_sync(0xFFFFFFFFu, p.x, j + 0);
            int s0 = __shfl_sync(0xFFFFFFFFu, p.y, j + 0);
            int e1 = __shfl_sync(0xFFFFFFFFu, p.x, j + 1);
            int s1 = __shfl_sync(0xFFFFFFFFu, p.y, j + 1);
            int e2 = __shfl_sync(0xFFFFFFFFu, p.x, j + 2);
            int s2 = __shfl_sync(0xFFFFFFFFu, p.y, j + 2);
            int e3 = __shfl_sync(0xFFFFFFFFu, p.x, j + 3);
            int s3 = __shfl_sync(0xFFFFFFFFu, p.y, j + 3);

            float4 ev0 = ldcs4(reinterpret_cast<const float4*>(ea + (long long)e0 * DIN) + lane);
            float4 ev1 = ldcs4(reinterpret_cast<const float4*>(ea + (long long)e1 * DIN) + lane);
            float4 ev2 = ldcs4(reinterpret_cast<const float4*>(ea + (long long)e2 * DIN) + lane);
            float4 ev3 = ldcs4(reinterpret_cast<const float4*>(ea + (long long)e3 * DIN) + lane);
            float4 xv0 = reinterpret_cast<const float4*>(x + (long long)s0 * DIN)[lane];
            float4 xv1 = reinterpret_cast<const float4*>(x + (long long)s1 * DIN)[lane];
            float4 xv2 = reinterpret_cast<const float4*>(x + (long long)s2 * DIN)[lane];
            float4 xv3 = reinterpret_cast<const float4*>(x + (long long)s3 * DIN)[lane];

            acc.x = fmaf(xv0.x, ev0.x, acc.x); acc.y = fmaf(xv0.y, ev0.y, acc.y);
            acc.z = fmaf(xv0.z, ev0.z, acc.z); acc.w = fmaf(xv0.w, ev0.w, acc.w);
            acc.x = fmaf(xv1.x, ev1.x, acc.x); acc.y = fmaf(xv1.y, ev1.y, acc.y);
            acc.z = fmaf(xv1.z, ev1.z, acc.z); acc.w = fmaf(xv1.w, ev1.w, acc.w);
            acc.x = fmaf(xv2.x, ev2.x, acc.x); acc.y = fmaf(xv2.y, ev2.y, acc.y);
            acc.z = fmaf(xv2.z, ev2.z, acc.z); acc.w = fmaf(xv2.w, ev2.w, acc.w);
            acc.x = fmaf(xv3.x, ev3.x, acc.x); acc.y = fmaf(xv3.y, ev3.y, acc.y);
            acc.z = fmaf(xv3.z, ev3.z, acc.z); acc.w = fmaf(xv3.w, ev3.w, acc.w);
        }
        for (; j < take; j++) {
            int e = __shfl_sync(0xFFFFFFFFu, p.x, j);
            int s = __shfl_sync(0xFFFFFFFFu, p.y, j);
            float4 ev = ldcs4(reinterpret_cast<const float4*>(ea + (long long)e * DIN) + lane);
            float4 xv = reinterpret_cast<const float4*>(x + (long long)s * DIN)[lane];
            acc.x = fmaf(xv.x, ev.x, acc.x);
            acc.y = fmaf(xv.y, ev.y, acc.y);
            acc.z = fmaf(xv.z, ev.z, acc.z);
            acc.w = fmaf(xv.w, ev.w, acc.w);
        }
    }
    int deg = end - beg;
    float inv = (deg > 0) ? (1.0f / (float)deg) : 0.f;
    acc.x *= inv; acc.y *= inv; acc.z *= inv; acc.w *= inv;

    // stage mean to smem, then project through W0_bot (lane -> oc pair 2*lane, 2*lane+1)
    reinterpret_cast<float4*>(sAcc[wid])[lane] = acc;
    __syncwarp();

    float2 pc = make_float2(0.f, 0.f);
    #pragma unroll 4
    for (int k = 0; k < DIN; k++) {
        float a = sAcc[wid][k];
        float2 w = *reinterpret_cast<const float2*>(&sW0b[k * HID + 2 * lane]);
        pc.x = fmaf(a, w.x, pc.x);
        pc.y = fmaf(a, w.y, pc.y);
    }
    reinterpret_cast<float2*>(hpart + (long long)warp * HID)[lane] = pc;
}

// ---------------- layer 0 dense: x @ W0_top + hpart, ReLU ----------------
// Half the FMAs of the old kernel: only k-chunks over x (2 x 64).
__global__ void layer0_mm_kernel(const float* __restrict__ x,
                                 const float* __restrict__ hpart,
                                 const float* __restrict__ W0,
                                 const float* __restrict__ b0,
                                 float* __restrict__ h,
                                 int N)
{
    __shared__ float sW[64 * HID];
    __shared__ float sF[64 * 64];

    int tid = threadIdx.x;
    int to = tid & 15;
    int tn = tid >> 4;
    int base = blockIdx.x * 64;

    // init accumulators from the aggregation projection
    float c[4][4];
    #pragma unroll
    for (int i = 0; i < 4; i++) {
        int node = base + 4 * tn + i;
        float4 p = make_float4(0.f, 0.f, 0.f, 0.f);
        if (node < N) p = reinterpret_cast<const float4*>(hpart + (long long)node * HID)[to];
        c[i][0] = p.x; c[i][1] = p.y; c[i][2] = p.z; c[i][3] = p.w;
    }

    for (int kc = 0; kc < 2; kc++) {
        {
            const float4* w4 = reinterpret_cast<const float4*>(W0 + kc * 64 * HID);
            float4* sw4 = reinterpret_cast<float4*>(sW);
            #pragma unroll
            for (int i = 0; i < 4; i++) sw4[tid + 256 * i] = w4[tid + 256 * i];
        }
        {
            int koff4 = kc * 16;
            for (int i = tid; i < 64 * 16; i += 256) {
                int ln = i >> 4;
                int kq = i & 15;
                int node = base + ln;
                float4 v = make_float4(0.f, 0.f, 0.f, 0.f);
                if (node < N)
                    v = reinterpret_cast<const float4*>(x + (long long)node * DIN)[koff4 + kq];
                reinterpret_cast<float4*>(sF + ln * 64)[kq] = v;
            }
        }
        __syncthreads();

        const float* fa0 = sF + (4 * tn + 0) * 64;
        const float* fa1 = sF + (4 * tn + 1) * 64;
        const float* fa2 = sF + (4 * tn + 2) * 64;
        const float* fa3 = sF + (4 * tn + 3) * 64;

        #pragma unroll 8
        for (int k = 0; k < 64; k++) {
            float4 b = reinterpret_cast<const float4*>(sW + k * HID)[to];
            float a0 = fa0[k], a1 = fa1[k], a2 = fa2[k], a3 = fa3[k];
            c[0][0] = fmaf(a0, b.x, c[0][0]); c[0][1] = fmaf(a0, b.y, c[0][1]);
            c[0][2] = fmaf(a0, b.z, c[0][2]); c[0][3] = fmaf(a0, b.w, c[0][3]);
            c[1][0] = fmaf(a1, b.x, c[1][0]); c[1][1] = fmaf(a1, b.y, c[1][1]);
            c[1][2] = fmaf(a1, b.z, c[1][2]); c[1][3] = fmaf(a1, b.w, c[1][3]);
            c[2][0] = fmaf(a2, b.x, c[2][0]); c[2][1] = fmaf(a2, b.y, c[2][1]);
            c[2][2] = fmaf(a2, b.z, c[2][2]); c[2][3] = fmaf(a2, b.w, c[2][3]);
            c[3][0] = fmaf(a3, b.x, c[3][0]); c[3][1] = fmaf(a3, b.y, c[3][1]);
            c[3][2] = fmaf(a3, b.z, c[3][2]); c[3][3] = fmaf(a3, b.w, c[3][3]);
        }
        __syncthreads();
    }

    float4 bias = reinterpret_cast<const float4*>(b0)[to];
    #pragma unroll
    for (int i = 0; i < 4; i++) {
        int node = base + 4 * tn + i;
        if (node < N) {
            float4 o;
            o.x = fmaxf(c[i][0] + bias.x, 0.f);
            o.y = fmaxf(c[i][1] + bias.y, 0.f);
            o.z = fmaxf(c[i][2] + bias.z, 0.f);
            o.w = fmaxf(c[i][3] + bias.w, 0.f);
            reinterpret_cast<float4*>(h + (long long)node * HID)[to] = o;
        }
    }
}

// ---------------- fused layer 1: half-warp float4, padded batches ----------------
__global__ void __launch_bounds__(256, 5)
agg1_fused_kernel(const float* __restrict__ h,
                  const float* __restrict__ ea,
                  const int2* __restrict__ perm,
                  const int* __restrict__ rowstart,
                  const float* __restrict__ W1,
                  const float* __restrict__ b1,
                  float* __restrict__ out,
                  int N)
{
    __shared__ float swB[2 * HID]; // W1 rows 64..127 (flat 128..255)
    __shared__ float swT[2 * HID]; // W1 rows 0..63   (flat 0..127)
    __shared__ float sb[DOUT];
    if (threadIdx.x < 2 * HID) {
        swT[threadIdx.x] = W1[threadIdx.x];
        swB[threadIdx.x] = W1[2 * HID + threadIdx.x];
    }
    if (threadIdx.x < DOUT) sb[threadIdx.x] = b1[threadIdx.x];
    __syncthreads();

    int warp = (blockIdx.x * blockDim.x + threadIdx.x) >> 5;
    int lane = threadIdx.x & 31;
    int half = lane >> 4;
    int sub  = lane & 15;
    if (warp >= N) return;

    int beg = rowstart[warp];
    int end = rowstart[warp + 1];

    float4 acc = make_float4(0.f, 0.f, 0.f, 0.f);
    for (int base = beg; base < end; base += 32) {
        int take = min(end - base, 32);
        int2 p = make_int2(0, 0);
        if (lane < take) p = perm[base + lane];

        for (int j = 0; j < take; j += 8) {
            int i0 = j + 4 * half;
            int tk1 = take - 1;
            int si0 = min(i0 + 0, tk1), si1 = min(i0 + 1, tk1);
            int si2 = min(i0 + 2, tk1), si3 = min(i0 + 3, tk1);
            bool v0 = (i0 + 0) < take, v1 = (i0 + 1) < take;
            bool v2 = (i0 + 2) < take, v3 = (i0 + 3) < take;

            int e0 = __shfl_sync(0xFFFFFFFFu, p.x, si0);
            int s0 = __shfl_sync(0xFFFFFFFFu, p.y, si0);
            int e1 = __shfl_sync(0xFFFFFFFFu, p.x, si1);
            int s1 = __shfl_sync(0xFFFFFFFFu, p.y, si1);
            int e2 = __shfl_sync(0xFFFFFFFFu, p.x, si2);
            int s2 = __shfl_sync(0xFFFFFFFFu, p.y, si2);
            int e3 = __shfl_sync(0xFFFFFFFFu, p.x, si3);
            int s3 = __shfl_sync(0xFFFFFFFFu, p.y, si3);

            float4 ev0 = ldcs4(reinterpret_cast<const float4*>(ea + (long long)e0 * HID) + sub);
            float4 ev1 = ldcs4(reinterpret_cast<const float4*>(ea + (long long)e1 * HID) + sub);
            float4 ev2 = ldcs4(reinterpret_cast<const float4*>(ea + (long long)e2 * HID) + sub);
            float4 ev3 = ldcs4(reinterpret_cast<const float4*>(ea + (long long)e3 * HID) + sub);
            float4 hv0 = reinterpret_cast<const float4*>(h + (long long)s0 * HID)[sub];
            float4 hv1 = reinterpret_cast<const float4*>(h + (long long)s1 * HID)[sub];
            float4 hv2 = reinterpret_cast<const float4*>(h + (long long)s2 * HID)[sub];
            float4 hv3 = reinterpret_cast<const float4*>(h + (long long)s3 * HID)[sub];

            if (!v0) hv0 = make_float4(0.f, 0.f, 0.f, 0.f);
            if (!v1) hv1 = make_float4(0.f, 0.f, 0.f, 0.f);
            if (!v2) hv2 = make_float4(0.f, 0.f, 0.f, 0.f);
            if (!v3) hv3 = make_float4(0.f, 0.f, 0.f, 0.f);

            acc.x = fmaf(hv0.x, ev0.x, acc.x); acc.y = fmaf(hv0.y, ev0.y, acc.y);
            acc.z = fmaf(hv0.z, ev0.z, acc.z); acc.w = fmaf(hv0.w, ev0.w, acc.w);
            acc.x = fmaf(hv1.x, ev1.x, acc.x); acc.y = fmaf(hv1.y, ev1.y, acc.y);
            acc.z = fmaf(hv1.z, ev1.z, acc.z); acc.w = fmaf(hv1.w, ev1.w, acc.w);
            acc.x = fmaf(hv2.x, ev2.x, acc.x); acc.y = fmaf(hv2.y, ev2.y, acc.y);
            acc.z = fmaf(hv2.z, ev2.z, acc.z); acc.w = fmaf(hv2.w, ev2.w, acc.w);
            acc.x = fmaf(hv3.x, ev3.x, acc.x); acc.y = fmaf(hv3.y, ev3.y, acc.y);
            acc.z = fmaf(hv3.z, ev3.z, acc.z); acc.w = fmaf(hv3.w, ev3.w, acc.w);
        }
    }

    acc.x += __shfl_xor_sync(0xFFFFFFFFu, acc.x, 16);
    acc.y += __shfl_xor_sync(0xFFFFFFFFu, acc.y, 16);
    acc.z += __shfl_xor_sync(0xFFFFFFFFu, acc.z, 16);
    acc.w += __shfl_xor_sync(0xFFFFFFFFu, acc.w, 16);

    int deg = end - beg;
    float inv = (deg > 0) ? (1.0f / (float)deg) : 0.f;

    float4 hd = reinterpret_cast<const float4*>(h + (long long)warp * HID)[sub];

    int c0 = 4 * sub;
    float r0 = inv * (acc.x * swB[(c0 + 0) * 2 + 0] + acc.y * swB[(c0 + 1) * 2 + 0]
                    + acc.z * swB[(c0 + 2) * 2 + 0] + acc.w * swB[(c0 + 3) * 2 + 0])
             +        hd.x * swT[(c0 + 0) * 2 + 0] + hd.y * swT[(c0 + 1) * 2 + 0]
             +        hd.z * swT[(c0 + 2) * 2 + 0] + hd.w * swT[(c0 + 3) * 2 + 0];
    float r1 = inv * (acc.x * swB[(c0 + 0) * 2 + 1] + acc.y * swB[(c0 + 1) * 2 + 1]
                    + acc.z * swB[(c0 + 2) * 2 + 1] + acc.w * swB[(c0 + 3) * 2 + 1])
             +        hd.x * swT[(c0 + 0) * 2 + 1] + hd.y * swT[(c0 + 1) * 2 + 1]
             +        hd.z * swT[(c0 + 2) * 2 + 1] + hd.w * swT[(c0 + 3) * 2 + 1];

    #pragma unroll
    for (int o = 8; o > 0; o >>= 1) {
        r0 += __shfl_xor_sync(0xFFFFFFFFu, r0, o);
        r1 += __shfl_xor_sync(0xFFFFFFFFu, r1, o);
    }
    if (lane == 0) {
        out[(long long)warp * DOUT + 0] = r0 + sb[0];
        out[(long long)warp * DOUT + 1] = r1 + sb[1];
    }
}

// ---------------------------------------------------------------------------
extern "C" void kernel_launch(void* const* d_in, const int* in_sizes, int n_in,
                              void* d_out, int out_size)
{
    const float* x   = (const float*)d_in[0];
    const int*   ei  = (const int*)d_in[1];
    const float* ea0 = (const float*)d_in[2];
    const float* ea1 = (const float*)d_in[3];
    const float* W0  = (const float*)d_in[4];
    const float* b0  = (const float*)d_in[5];
    const float* W1  = (const float*)d_in[6];
    const float* b1  = (const float*)d_in[7];
    float* out = (float*)d_out;

    const int N = in_sizes[0] / DIN;
    const int E = in_sizes[1] / 2;

    int *hist_p, *rowstart_p, *cursor_p;
    int2 *perm_p;
    float *hpart_p, *h_p;
    cudaGetSymbolAddress((void**)&hist_p,     g_hist);
    cudaGetSymbolAddress((void**)&rowstart_p, g_rowstart);
    cudaGetSymbolAddress((void**)&cursor_p,   g_cursor);
    cudaGetSymbolAddress((void**)&perm_p,     g_perm);
    cudaGetSymbolAddress((void**)&hpart_p,    g_hpart);
    cudaGetSymbolAddress((void**)&h_p,        g_h);

    // launch 0: histogram (hist is zero on entry; scan re-zeroes)
    hist_kernel<<<(E + 255) / 256, 256>>>(ei, hist_p, E);
    // launch 1: scan
    scan_kernel<<<1, 1024>>>(hist_p, rowstart_p, cursor_p, N, E);
    // launch 2: perm build
    build_kernel<<<(E + 255) / 256, 256>>>(ei, cursor_p, perm_p, E);
    // launch 3: fused aggregation + W0_bot projection
    agg0proj_kernel<<<(N * 32 + 255) / 256, 256>>>(x, ea0, perm_p, rowstart_p,
                                                   W0, hpart_p, N);
    // launch 4: layer0 GEMM (x @ W0_top + hpart, relu)
    layer0_mm_kernel<<<(N + 63) / 64, 256>>>(x, hpart_p, W0, b0, h_p, N);
    // launch 5: fused layer-1 (profiled by ncu -s 5 -c 1)
    agg1_fused_kernel<<<(N * 32 + 255) / 256, 256>>>(h_p, ea1, perm_p, rowstart_p,
                                                     W1, b1, out, N);
}

// round 16
// speedup vs baseline: 1.2055x; 1.2055x over previous
#include <cuda_runtime.h>
#include <cuda_bf16.h>
#include <stdint.h>

#define N_NODES 100000
#define E_EDGES 1600000
#define DIN 128
#define HID 64
#define DOUT 2

// Scratch (device globals; no allocation allowed). Zero-initialized at load.
// INVARIANT: g_hist is zero at entry to every kernel_launch call.
__device__ int    g_hist[N_NODES];
__device__ int    g_rowstart[N_NODES + 1];
__device__ int    g_cursor[N_NODES];
__device__ int2   g_perm[E_EDGES];                 // {edge, src} sorted by dst
__device__ float  g_agg0[(size_t)N_NODES * DIN];   // layer-0 MEAN aggregation
__device__ float  g_xpart[(size_t)N_NODES * HID];  // x @ W0_top + b0
__device__ float  g_h[(size_t)N_NODES * HID];      // hidden activations

__device__ __forceinline__ float4 ldcs4(const float4* p) {
    float4 v;
    asm volatile("ld.global.cs.v4.f32 {%0,%1,%2,%3}, [%4];"
                 : "=f"(v.x), "=f"(v.y), "=f"(v.z), "=f"(v.w) : "l"(p));
    return v;
}

// ---------------- histogram over dst ----------------
__global__ void hist_kernel(const int* __restrict__ ei, int* __restrict__ hist, int E)
{
    int e = blockIdx.x * blockDim.x + threadIdx.x;
    if (e < E) atomicAdd(&hist[ei[E + e]], 1);
}

// ---------------- single-block exclusive scan (consumes + re-zeroes hist) ----------------
__global__ void scan_kernel(int* __restrict__ hist,
                            int* __restrict__ rowstart, int* __restrict__ cursor,
                            int N, int E)
{
    __shared__ int warpsum[32];
    __shared__ int s_carry;
    int tid  = threadIdx.x;
    int lane = tid & 31;
    int wid  = tid >> 5;
    if (tid == 0) s_carry = 0;
    __syncthreads();

    int v = (tid < N) ? hist[tid] : 0;
    for (int base = 0; base < N; base += 1024) {
        int inext = base + 1024 + tid;
        int vnext = (inext < N && base + 1024 < N) ? hist[inext] : 0;

        int incl = v;
        #pragma unroll
        for (int off = 1; off < 32; off <<= 1) {
            int t = __shfl_up_sync(0xFFFFFFFFu, incl, off);
            if (lane >= off) incl += t;
        }
        if (lane == 31) warpsum[wid] = incl;
        __syncthreads();
        if (wid == 0) {
            int w = (lane < 32) ? warpsum[lane] : 0;
            int wi = w;
            #pragma unroll
            for (int off = 1; off < 32; off <<= 1) {
                int t = __shfl_up_sync(0xFFFFFFFFu, wi, off);
                if (lane >= off) wi += t;
            }
            warpsum[lane] = wi - w;
        }
        __syncthreads();
        int carry = s_carry;
        int excl = incl - v + warpsum[wid] + carry;
        int i = base + tid;
        if (i < N) {
            rowstart[i] = excl;
            cursor[i]   = excl;
            hist[i]     = 0;
        }
        __syncthreads();
        if (tid == 1023) s_carry = excl + v;
        __syncthreads();
        v = vnext;
    }
    if (tid == 0) rowstart[N] = E;
}

__global__ void build_kernel(const int* __restrict__ ei, int* __restrict__ cursor,
                             int2* __restrict__ perm, int E)
{
    int e = blockIdx.x * blockDim.x + threadIdx.x;
    if (e >= E) return;
    int s = ei[e];
    int d = ei[E + e];
    int pos = atomicAdd(&cursor[d], 1);
    perm[pos] = make_int2(e, s);
}

// ---------------- layer 0 aggregation: warp per dst, 4-edge batched loads ----------------
__global__ void __launch_bounds__(256, 6)
agg0_kernel(const float* __restrict__ x,
            const float* __restrict__ ea,
            const int2* __restrict__ perm,
            const int* __restrict__ rowstart,
            float* __restrict__ agg0,
            int N)
{
    int warp = (blockIdx.x * blockDim.x + threadIdx.x) >> 5;
    int lane = threadIdx.x & 31;
    if (warp >= N) return;

    int beg = rowstart[warp];
    int end = rowstart[warp + 1];

    float4 acc = make_float4(0.f, 0.f, 0.f, 0.f);
    for (int base = beg; base < end; base += 32) {
        int take = min(end - base, 32);
        int2 p = make_int2(0, 0);
        if (lane < take) p = perm[base + lane];

        int j = 0;
        for (; j + 4 <= take; j += 4) {
            int e0 = __shfl_sync(0xFFFFFFFFu, p.x, j + 0);
            int s0 = __shfl_sync(0xFFFFFFFFu, p.y, j + 0);
            int e1 = __shfl_sync(0xFFFFFFFFu, p.x, j + 1);
            int s1 = __shfl_sync(0xFFFFFFFFu, p.y, j + 1);
            int e2 = __shfl_sync(0xFFFFFFFFu, p.x, j + 2);
            int s2 = __shfl_sync(0xFFFFFFFFu, p.y, j + 2);
            int e3 = __shfl_sync(0xFFFFFFFFu, p.x, j + 3);
            int s3 = __shfl_sync(0xFFFFFFFFu, p.y, j + 3);

            float4 ev0 = ldcs4(reinterpret_cast<const float4*>(ea + (long long)e0 * DIN) + lane);
            float4 ev1 = ldcs4(reinterpret_cast<const float4*>(ea + (long long)e1 * DIN) + lane);
            float4 ev2 = ldcs4(reinterpret_cast<const float4*>(ea + (long long)e2 * DIN) + lane);
            float4 ev3 = ldcs4(reinterpret_cast<const float4*>(ea + (long long)e3 * DIN) + lane);
            float4 xv0 = reinterpret_cast<const float4*>(x + (long long)s0 * DIN)[lane];
            float4 xv1 = reinterpret_cast<const float4*>(x + (long long)s1 * DIN)[lane];
            float4 xv2 = reinterpret_cast<const float4*>(x + (long long)s2 * DIN)[lane];
            float4 xv3 = reinterpret_cast<const float4*>(x + (long long)s3 * DIN)[lane];

            acc.x = fmaf(xv0.x, ev0.x, acc.x); acc.y = fmaf(xv0.y, ev0.y, acc.y);
            acc.z = fmaf(xv0.z, ev0.z, acc.z); acc.w = fmaf(xv0.w, ev0.w, acc.w);
            acc.x = fmaf(xv1.x, ev1.x, acc.x); acc.y = fmaf(xv1.y, ev1.y, acc.y);
            acc.z = fmaf(xv1.z, ev1.z, acc.z); acc.w = fmaf(xv1.w, ev1.w, acc.w);
            acc.x = fmaf(xv2.x, ev2.x, acc.x); acc.y = fmaf(xv2.y, ev2.y, acc.y);
            acc.z = fmaf(xv2.z, ev2.z, acc.z); acc.w = fmaf(xv2.w, ev2.w, acc.w);
            acc.x = fmaf(xv3.x, ev3.x, acc.x); acc.y = fmaf(xv3.y, ev3.y, acc.y);
            acc.z = fmaf(xv3.z, ev3.z, acc.z); acc.w = fmaf(xv3.w, ev3.w, acc.w);
        }
        for (; j < take; j++) {
            int e = __shfl_sync(0xFFFFFFFFu, p.x, j);
            int s = __shfl_sync(0xFFFFFFFFu, p.y, j);
            float4 ev = ldcs4(reinterpret_cast<const float4*>(ea + (long long)e * DIN) + lane);
            float4 xv = reinterpret_cast<const float4*>(x + (long long)s * DIN)[lane];
            acc.x = fmaf(xv.x, ev.x, acc.x);
            acc.y = fmaf(xv.y, ev.y, acc.y);
            acc.z = fmaf(xv.z, ev.z, acc.z);
            acc.w = fmaf(xv.w, ev.w, acc.w);
        }
    }
    int deg = end - beg;
    float inv = (deg > 0) ? (1.0f / (float)deg) : 0.f;
    acc.x *= inv; acc.y *= inv; acc.z *= inv; acc.w *= inv;
    reinterpret_cast<float4*>(agg0 + (long long)warp * DIN)[lane] = acc;
}

// ---------------- xpart: xp = x @ W0_top + b0 (runs on side stream) ----------------
__global__ void xpart_kernel(const float* __restrict__ x,
                             const float* __restrict__ W0,
                             const float* __restrict__ b0,
                             float* __restrict__ xp,
                             int N)
{
    __shared__ float sW[64 * HID];
    __shared__ float sF[64 * 64];

    int tid = threadIdx.x;
    int to = tid & 15;
    int tn = tid >> 4;
    int base = blockIdx.x * 64;

    float4 bias = reinterpret_cast<const float4*>(b0)[to];
    float c[4][4];
    #pragma unroll
    for (int i = 0; i < 4; i++) {
        c[i][0] = bias.x; c[i][1] = bias.y; c[i][2] = bias.z; c[i][3] = bias.w;
    }

    for (int kc = 0; kc < 2; kc++) {
        {
            const float4* w4 = reinterpret_cast<const float4*>(W0 + kc * 64 * HID);
            float4* sw4 = reinterpret_cast<float4*>(sW);
            #pragma unroll
            for (int i = 0; i < 4; i++) sw4[tid + 256 * i] = w4[tid + 256 * i];
        }
        {
            int koff4 = kc * 16;
            for (int i = tid; i < 64 * 16; i += 256) {
                int ln = i >> 4;
                int kq = i & 15;
                int node = base + ln;
                float4 v = make_float4(0.f, 0.f, 0.f, 0.f);
                if (node < N)
                    v = reinterpret_cast<const float4*>(x + (long long)node * DIN)[koff4 + kq];
                reinterpret_cast<float4*>(sF + ln * 64)[kq] = v;
            }
        }
        __syncthreads();

        const float* fa0 = sF + (4 * tn + 0) * 64;
        const float* fa1 = sF + (4 * tn + 1) * 64;
        const float* fa2 = sF + (4 * tn + 2) * 64;
        const float* fa3 = sF + (4 * tn + 3) * 64;

        #pragma unroll 8
        for (int k = 0; k < 64; k++) {
            float4 b = reinterpret_cast<const float4*>(sW + k * HID)[to];
            float a0 = fa0[k], a1 = fa1[k], a2 = fa2[k], a3 = fa3[k];
            c[0][0] = fmaf(a0, b.x, c[0][0]); c[0][1] = fmaf(a0, b.y, c[0][1]);
            c[0][2] = fmaf(a0, b.z, c[0][2]); c[0][3] = fmaf(a0, b.w, c[0][3]);
            c[1][0] = fmaf(a1, b.x, c[1][0]); c[1][1] = fmaf(a1, b.y, c[1][1]);
            c[1][2] = fmaf(a1, b.z, c[1][2]); c[1][3] = fmaf(a1, b.w, c[1][3]);
            c[2][0] = fmaf(a2, b.x, c[2][0]); c[2][1] = fmaf(a2, b.y, c[2][1]);
            c[2][2] = fmaf(a2, b.z, c[2][2]); c[2][3] = fmaf(a2, b.w, c[2][3]);
            c[3][0] = fmaf(a3, b.x, c[3][0]); c[3][1] = fmaf(a3, b.y, c[3][1]);
            c[3][2] = fmaf(a3, b.z, c[3][2]); c[3][3] = fmaf(a3, b.w, c[3][3]);
        }
        __syncthreads();
    }

    #pragma unroll
    for (int i = 0; i < 4; i++) {
        int node = base + 4 * tn + i;
        if (node < N) {
            float4 o = make_float4(c[i][0], c[i][1], c[i][2], c[i][3]);
            reinterpret_cast<float4*>(xp + (long long)node * HID)[to] = o;
        }
    }
}

// ---------------- combine: h = relu(xp + agg0 @ W0_bot) ----------------
__global__ void combine_kernel(const float* __restrict__ agg0,
                               const float* __restrict__ xp,
                               const float* __restrict__ W0,
                               float* __restrict__ h,
                               int N)
{
    __shared__ float sW[64 * HID];
    __shared__ float sF[64 * 64];

    int tid = threadIdx.x;
    int to = tid & 15;
    int tn = tid >> 4;
    int base = blockIdx.x * 64;

    float c[4][4];
    #pragma unroll
    for (int i = 0; i < 4; i++) {
        int node = base + 4 * tn + i;
        float4 p = make_float4(0.f, 0.f, 0.f, 0.f);
        if (node < N) p = reinterpret_cast<const float4*>(xp + (long long)node * HID)[to];
        c[i][0] = p.x; c[i][1] = p.y; c[i][2] = p.z; c[i][3] = p.w;
    }

    for (int kc = 0; kc < 2; kc++) {
        {
            // W0 rows 128..255 (bottom half)
            const float4* w4 = reinterpret_cast<const float4*>(W0 + (2 + kc) * 64 * HID);
            float4* sw4 = reinterpret_cast<float4*>(sW);
            #pragma unroll
            for (int i = 0; i < 4; i++) sw4[tid + 256 * i] = w4[tid + 256 * i];
        }
        {
            int koff4 = kc * 16;
            for (int i = tid; i < 64 * 16; i += 256) {
                int ln = i >> 4;
                int kq = i & 15;
                int node = base + ln;
                float4 v = make_float4(0.f, 0.f, 0.f, 0.f);
                if (node < N)
                    v = reinterpret_cast<const float4*>(agg0 + (long long)node * DIN)[koff4 + kq];
                reinterpret_cast<float4*>(sF + ln * 64)[kq] = v;
            }
        }
        __syncthreads();

        const float* fa0 = sF + (4 * tn + 0) * 64;
        const float* fa1 = sF + (4 * tn + 1) * 64;
        const float* fa2 = sF + (4 * tn + 2) * 64;
        const float* fa3 = sF + (4 * tn + 3) * 64;

        #pragma unroll 8
        for (int k = 0; k < 64; k++) {
            float4 b = reinterpret_cast<const float4*>(sW + k * HID)[to];
            float a0 = fa0[k], a1 = fa1[k], a2 = fa2[k], a3 = fa3[k];
            c[0][0] = fmaf(a0, b.x, c[0][0]); c[0][1] = fmaf(a0, b.y, c[0][1]);
            c[0][2] = fmaf(a0, b.z, c[0][2]); c[0][3] = fmaf(a0, b.w, c[0][3]);
            c[1][0] = fmaf(a1, b.x, c[1][0]); c[1][1] = fmaf(a1, b.y, c[1][1]);
            c[1][2] = fmaf(a1, b.z, c[1][2]); c[1][3] = fmaf(a1, b.w, c[1][3]);
            c[2][0] = fmaf(a2, b.x, c[2][0]); c[2][1] = fmaf(a2, b.y, c[2][1]);
            c[2][2] = fmaf(a2, b.z, c[2][2]); c[2][3] = fmaf(a2, b.w, c[2][3]);
            c[3][0] = fmaf(a3, b.x, c[3][0]); c[3][1] = fmaf(a3, b.y, c[3][1]);
            c[3][2] = fmaf(a3, b.z, c[3][2]); c[3][3] = fmaf(a3, b.w, c[3][3]);
        }
        __syncthreads();
    }

    #pragma unroll
    for (int i = 0; i < 4; i++) {
        int node = base + 4 * tn + i;
        if (node < N) {
            float4 o;
            o.x = fmaxf(c[i][0], 0.f);
            o.y = fmaxf(c[i][1], 0.f);
            o.z = fmaxf(c[i][2], 0.f);
            o.w = fmaxf(c[i][3], 0.f);
            reinterpret_cast<float4*>(h + (long long)node * HID)[to] = o;
        }
    }
}

// ---------------- fused layer 1: half-warp float4, padded batches ----------------
__global__ void __launch_bounds__(256, 5)
agg1_fused_kernel(const float* __restrict__ h,
                  const float* __restrict__ ea,
                  const int2* __restrict__ perm,
                  const int* __restrict__ rowstart,
                  const float* __restrict__ W1,
                  const float* __restrict__ b1,
                  float* __restrict__ out,
                  int N)
{
    __shared__ float swB[2 * HID];
    __shared__ float swT[2 * HID];
    __shared__ float sb[DOUT];
    if (threadIdx.x < 2 * HID) {
        swT[threadIdx.x] = W1[threadIdx.x];
        swB[threadIdx.x] = W1[2 * HID + threadIdx.x];
    }
    if (threadIdx.x < DOUT) sb[threadIdx.x] = b1[threadIdx.x];
    __syncthreads();

    int warp = (blockIdx.x * blockDim.x + threadIdx.x) >> 5;
    int lane = threadIdx.x & 31;
    int half = lane >> 4;
    int sub  = lane & 15;
    if (warp >= N) return;

    int beg = rowstart[warp];
    int end = rowstart[warp + 1];

    float4 acc = make_float4(0.f, 0.f, 0.f, 0.f);
    for (int base = beg; base < end; base += 32) {
        int take = min(end - base, 32);
        int2 p = make_int2(0, 0);
        if (lane < take) p = perm[base + lane];

        for (int j = 0; j < take; j += 8) {
            int i0 = j + 4 * half;
            int tk1 = take - 1;
            int si0 = min(i0 + 0, tk1), si1 = min(i0 + 1, tk1);
            int si2 = min(i0 + 2, tk1), si3 = min(i0 + 3, tk1);
            bool v0 = (i0 + 0) < take, v1 = (i0 + 1) < take;
            bool v2 = (i0 + 2) < take, v3 = (i0 + 3) < take;

            int e0 = __shfl_sync(0xFFFFFFFFu, p.x, si0);
            int s0 = __shfl_sync(0xFFFFFFFFu, p.y, si0);
            int e1 = __shfl_sync(0xFFFFFFFFu, p.x, si1);
            int s1 = __shfl_sync(0xFFFFFFFFu, p.y, si1);
            int e2 = __shfl_sync(0xFFFFFFFFu, p.x, si2);
            int s2 = __shfl_sync(0xFFFFFFFFu, p.y, si2);
            int e3 = __shfl_sync(0xFFFFFFFFu, p.x, si3);
            int s3 = __shfl_sync(0xFFFFFFFFu, p.y, si3);

            float4 ev0 = ldcs4(reinterpret_cast<const float4*>(ea + (long long)e0 * HID) + sub);
            float4 ev1 = ldcs4(reinterpret_cast<const float4*>(ea + (long long)e1 * HID) + sub);
            float4 ev2 = ldcs4(reinterpret_cast<const float4*>(ea + (long long)e2 * HID) + sub);
            float4 ev3 = ldcs4(reinterpret_cast<const float4*>(ea + (long long)e3 * HID) + sub);
            float4 hv0 = reinterpret_cast<const float4*>(h + (long long)s0 * HID)[sub];
            float4 hv1 = reinterpret_cast<const float4*>(h + (long long)s1 * HID)[sub];
            float4 hv2 = reinterpret_cast<const float4*>(h + (long long)s2 * HID)[sub];
            float4 hv3 = reinterpret_cast<const float4*>(h + (long long)s3 * HID)[sub];

            if (!v0) hv0 = make_float4(0.f, 0.f, 0.f, 0.f);
            if (!v1) hv1 = make_float4(0.f, 0.f, 0.f, 0.f);
            if (!v2) hv2 = make_float4(0.f, 0.f, 0.f, 0.f);
            if (!v3) hv3 = make_float4(0.f, 0.f, 0.f, 0.f);

            acc.x = fmaf(hv0.x, ev0.x, acc.x); acc.y = fmaf(hv0.y, ev0.y, acc.y);
            acc.z = fmaf(hv0.z, ev0.z, acc.z); acc.w = fmaf(hv0.w, ev0.w, acc.w);
            acc.x = fmaf(hv1.x, ev1.x, acc.x); acc.y = fmaf(hv1.y, ev1.y, acc.y);
            acc.z = fmaf(hv1.z, ev1.z, acc.z); acc.w = fmaf(hv1.w, ev1.w, acc.w);
            acc.x = fmaf(hv2.x, ev2.x, acc.x); acc.y = fmaf(hv2.y, ev2.y, acc.y);
            acc.z = fmaf(hv2.z, ev2.z, acc.z); acc.w = fmaf(hv2.w, ev2.w, acc.w);
            acc.x = fmaf(hv3.x, ev3.x, acc.x); acc.y = fmaf(hv3.y, ev3.y, acc.y);
            acc.z = fmaf(hv3.z, ev3.z, acc.z); acc.w = fmaf(hv3.w, ev3.w, acc.w);
        }
    }

    acc.x += __shfl_xor_sync(0xFFFFFFFFu, acc.x, 16);
    acc.y += __shfl_xor_sync(0xFFFFFFFFu, acc.y, 16);
    acc.z += __shfl_xor_sync(0xFFFFFFFFu, acc.z, 16);
    acc.w += __shfl_xor_sync(0xFFFFFFFFu, acc.w, 16);

    int deg = end - beg;
    float inv = (deg > 0) ? (1.0f / (float)deg) : 0.f;

    float4 hd = reinterpret_cast<const float4*>(h + (long long)warp * HID)[sub];

    int c0 = 4 * sub;
    float r0 = inv * (acc.x * swB[(c0 + 0) * 2 + 0] + acc.y * swB[(c0 + 1) * 2 + 0]
                    + acc.z * swB[(c0 + 2) * 2 + 0] + acc.w * swB[(c0 + 3) * 2 + 0])
             +        hd.x * swT[(c0 + 0) * 2 + 0] + hd.y * swT[(c0 + 1) * 2 + 0]
             +        hd.z * swT[(c0 + 2) * 2 + 0] + hd.w * swT[(c0 + 3) * 2 + 0];
    float r1 = inv * (acc.x * swB[(c0 + 0) * 2 + 1] + acc.y * swB[(c0 + 1) * 2 + 1]
                    + acc.z * swB[(c0 + 2) * 2 + 1] + acc.w * swB[(c0 + 3) * 2 + 1])
             +        hd.x * swT[(c0 + 0) * 2 + 1] + hd.y * swT[(c0 + 1) * 2 + 1]
             +        hd.z * swT[(c0 + 2) * 2 + 1] + hd.w * swT[(c0 + 3) * 2 + 1];

    #pragma unroll
    for (int o = 8; o > 0; o >>= 1) {
        r0 += __shfl_xor_sync(0xFFFFFFFFu, r0, o);
        r1 += __shfl_xor_sync(0xFFFFFFFFu, r1, o);
    }
    if (lane == 0) {
        out[(long long)warp * DOUT + 0] = r0 + sb[0];
        out[(long long)warp * DOUT + 1] = r1 + sb[1];
    }
}

// ---------------------------------------------------------------------------
extern "C" void kernel_launch(void* const* d_in, const int* in_sizes, int n_in,
                              void* d_out, int out_size)
{
    const float* x   = (const float*)d_in[0];
    const int*   ei  = (const int*)d_in[1];
    const float* ea0 = (const float*)d_in[2];
    const float* ea1 = (const float*)d_in[3];
    const float* W0  = (const float*)d_in[4];
    const float* b0  = (const float*)d_in[5];
    const float* W1  = (const float*)d_in[6];
    const float* b1  = (const float*)d_in[7];
    float* out = (float*)d_out;

    const int N = in_sizes[0] / DIN;
    const int E = in_sizes[1] / 2;

    int *hist_p, *rowstart_p, *cursor_p;
    int2 *perm_p;
    float *agg0_p, *xpart_p, *h_p;
    cudaGetSymbolAddress((void**)&hist_p,     g_hist);
    cudaGetSymbolAddress((void**)&rowstart_p, g_rowstart);
    cudaGetSymbolAddress((void**)&cursor_p,   g_cursor);
    cudaGetSymbolAddress((void**)&perm_p,     g_perm);
    cudaGetSymbolAddress((void**)&agg0_p,     g_agg0);
    cudaGetSymbolAddress((void**)&xpart_p,    g_xpart);
    cudaGetSymbolAddress((void**)&h_p,        g_h);

    // side stream + fork/join events (host-side objects only; leaked across the
    // harness's ~2 calls — no device memory is allocated)
    cudaStream_t s2;
    cudaEvent_t evA, evB;
    cudaStreamCreateWithFlags(&s2, cudaStreamNonBlocking);
    cudaEventCreateWithFlags(&evA, cudaEventDisableTiming);
    cudaEventCreateWithFlags(&evB, cudaEventDisableTiming);

    // fork: xpart (x @ W0_top + b0) runs concurrently with binning + agg0
    cudaEventRecord(evA, 0);
    cudaStreamWaitEvent(s2, evA, 0);
    xpart_kernel<<<(N + 63) / 64, 256, 0, s2>>>(x, W0, b0, xpart_p, N);
    cudaEventRecord(evB, s2);

    // main stream: binning chain + layer-0 aggregation
    hist_kernel<<<(E + 255) / 256, 256>>>(ei, hist_p, E);
    scan_kernel<<<1, 1024>>>(hist_p, rowstart_p, cursor_p, N, E);
    build_kernel<<<(E + 255) / 256, 256>>>(ei, cursor_p, perm_p, E);
    agg0_kernel<<<(N * 32 + 255) / 256, 256>>>(x, ea0, perm_p, rowstart_p, agg0_p, N);

    // join: combine needs xpart
    cudaStreamWaitEvent(0, evB, 0);
    combine_kernel<<<(N + 63) / 64, 256>>>(agg0_p, xpart_p, W0, h_p, N);

    // fused layer-1
    agg1_fused_kernel<<<(N * 32 + 255) / 256, 256>>>(h_p, ea1, perm_p, rowstart_p,
                                                     W1, b1, out, N);
}

// round 17
// speedup vs baseline: 1.2311x; 1.0213x over previous
#include <cuda_runtime.h>
#include <cuda_bf16.h>
#include <stdint.h>

#define N_NODES 100000
#define E_EDGES 1600000
#define DIN 128
#define HID 64
#define DOUT 2

// Scratch (device globals; no allocation allowed). Zero-initialized at load.
// INVARIANT: g_hist is zero at entry to every kernel_launch call.
__device__ int    g_hist[N_NODES];
__device__ int    g_rowstart[N_NODES + 1];
__device__ int    g_cursor[N_NODES];
__device__ int2   g_perm[E_EDGES];                 // {edge, src} sorted by dst
__device__ float  g_agg0[(size_t)N_NODES * DIN];   // layer-0 MEAN aggregation
__device__ float  g_xpart[(size_t)N_NODES * HID];  // x @ W0_top + b0
__device__ float  g_h[(size_t)N_NODES * HID];      // hidden activations

__device__ __forceinline__ float4 ldcs4(const float4* p) {
    float4 v;
    asm volatile("ld.global.cs.v4.f32 {%0,%1,%2,%3}, [%4];"
                 : "=f"(v.x), "=f"(v.y), "=f"(v.z), "=f"(v.w) : "l"(p));
    return v;
}

// ---------------- histogram over dst: 4 edges per thread (MLP=4) ----------------
__global__ void hist_kernel(const int* __restrict__ ei, int* __restrict__ hist, int E)
{
    int q = blockIdx.x * blockDim.x + threadIdx.x;   // quad index
    int base = q * 4;
    if (base + 4 <= E) {
        int4 d = *reinterpret_cast<const int4*>(ei + E + base);
        atomicAdd(&hist[d.x], 1);
        atomicAdd(&hist[d.y], 1);
        atomicAdd(&hist[d.z], 1);
        atomicAdd(&hist[d.w], 1);
    } else if (base < E) {
        for (int e = base; e < E; e++) atomicAdd(&hist[ei[E + e]], 1);
    }
}

// ---------------- single-block exclusive scan (consumes + re-zeroes hist) ----------------
__global__ void scan_kernel(int* __restrict__ hist,
                            int* __restrict__ rowstart, int* __restrict__ cursor,
                            int N, int E)
{
    __shared__ int warpsum[32];
    __shared__ int s_carry;
    int tid  = threadIdx.x;
    int lane = tid & 31;
    int wid  = tid >> 5;
    if (tid == 0) s_carry = 0;
    __syncthreads();

    int v = (tid < N) ? hist[tid] : 0;
    for (int base = 0; base < N; base += 1024) {
        int inext = base + 1024 + tid;
        int vnext = (inext < N && base + 1024 < N) ? hist[inext] : 0;

        int incl = v;
        #pragma unroll
        for (int off = 1; off < 32; off <<= 1) {
            int t = __shfl_up_sync(0xFFFFFFFFu, incl, off);
            if (lane >= off) incl += t;
        }
        if (lane == 31) warpsum[wid] = incl;
        __syncthreads();
        if (wid == 0) {
            int w = (lane < 32) ? warpsum[lane] : 0;
            int wi = w;
            #pragma unroll
            for (int off = 1; off < 32; off <<= 1) {
                int t = __shfl_up_sync(0xFFFFFFFFu, wi, off);
                if (lane >= off) wi += t;
            }
            warpsum[lane] = wi - w;
        }
        __syncthreads();
        int carry = s_carry;
        int excl = incl - v + warpsum[wid] + carry;
        int i = base + tid;
        if (i < N) {
            rowstart[i] = excl;
            cursor[i]   = excl;
            hist[i]     = 0;
        }
        __syncthreads();
        if (tid == 1023) s_carry = excl + v;
        __syncthreads();
        v = vnext;
    }
    if (tid == 0) rowstart[N] = E;
}

// ---------------- perm build: 4 edges per thread (MLP=4) ----------------
__global__ void build_kernel(const int* __restrict__ ei, int* __restrict__ cursor,
                             int2* __restrict__ perm, int E)
{
    int q = blockIdx.x * blockDim.x + threadIdx.x;
    int base = q * 4;
    if (base + 4 <= E) {
        int4 s = *reinterpret_cast<const int4*>(ei + base);
        int4 d = *reinterpret_cast<const int4*>(ei + E + base);
        int p0 = atomicAdd(&cursor[d.x], 1);
        int p1 = atomicAdd(&cursor[d.y], 1);
        int p2 = atomicAdd(&cursor[d.z], 1);
        int p3 = atomicAdd(&cursor[d.w], 1);
        perm[p0] = make_int2(base + 0, s.x);
        perm[p1] = make_int2(base + 1, s.y);
        perm[p2] = make_int2(base + 2, s.z);
        perm[p3] = make_int2(base + 3, s.w);
    } else if (base < E) {
        for (int e = base; e < E; e++) {
            int s = ei[e];
            int d = ei[E + e];
            int pos = atomicAdd(&cursor[d], 1);
            perm[pos] = make_int2(e, s);
        }
    }
}

// ---------------- layer 0 aggregation: warp per dst, 4-edge batched loads ----------------
__global__ void __launch_bounds__(256, 6)
agg0_kernel(const float* __restrict__ x,
            const float* __restrict__ ea,
            const int2* __restrict__ perm,
            const int* __restrict__ rowstart,
            float* __restrict__ agg0,
            int N)
{
    int warp = (blockIdx.x * blockDim.x + threadIdx.x) >> 5;
    int lane = threadIdx.x & 31;
    if (warp >= N) return;

    int beg = rowstart[warp];
    int end = rowstart[warp + 1];

    float4 acc = make_float4(0.f, 0.f, 0.f, 0.f);
    for (int base = beg; base < end; base += 32) {
        int take = min(end - base, 32);
        int2 p = make_int2(0, 0);
        if (lane < take) p = perm[base + lane];

        int j = 0;
        for (; j + 4 <= take; j += 4) {
            int e0 = __shfl_sync(0xFFFFFFFFu, p.x, j + 0);
            int s0 = __shfl_sync(0xFFFFFFFFu, p.y, j + 0);
            int e1 = __shfl_sync(0xFFFFFFFFu, p.x, j + 1);
            int s1 = __shfl_sync(0xFFFFFFFFu, p.y, j + 1);
            int e2 = __shfl_sync(0xFFFFFFFFu, p.x, j + 2);
            int s2 = __shfl_sync(0xFFFFFFFFu, p.y, j + 2);
            int e3 = __shfl_sync(0xFFFFFFFFu, p.x, j + 3);
            int s3 = __shfl_sync(0xFFFFFFFFu, p.y, j + 3);

            float4 ev0 = ldcs4(reinterpret_cast<const float4*>(ea + (long long)e0 * DIN) + lane);
            float4 ev1 = ldcs4(reinterpret_cast<const float4*>(ea + (long long)e1 * DIN) + lane);
            float4 ev2 = ldcs4(reinterpret_cast<const float4*>(ea + (long long)e2 * DIN) + lane);
            float4 ev3 = ldcs4(reinterpret_cast<const float4*>(ea + (long long)e3 * DIN) + lane);
            float4 xv0 = reinterpret_cast<const float4*>(x + (long long)s0 * DIN)[lane];
            float4 xv1 = reinterpret_cast<const float4*>(x + (long long)s1 * DIN)[lane];
            float4 xv2 = reinterpret_cast<const float4*>(x + (long long)s2 * DIN)[lane];
            float4 xv3 = reinterpret_cast<const float4*>(x + (long long)s3 * DIN)[lane];

            acc.x = fmaf(xv0.x, ev0.x, acc.x); acc.y = fmaf(xv0.y, ev0.y, acc.y);
            acc.z = fmaf(xv0.z, ev0.z, acc.z); acc.w = fmaf(xv0.w, ev0.w, acc.w);
            acc.x = fmaf(xv1.x, ev1.x, acc.x); acc.y = fmaf(xv1.y, ev1.y, acc.y);
            acc.z = fmaf(xv1.z, ev1.z, acc.z); acc.w = fmaf(xv1.w, ev1.w, acc.w);
            acc.x = fmaf(xv2.x, ev2.x, acc.x); acc.y = fmaf(xv2.y, ev2.y, acc.y);
            acc.z = fmaf(xv2.z, ev2.z, acc.z); acc.w = fmaf(xv2.w, ev2.w, acc.w);
            acc.x = fmaf(xv3.x, ev3.x, acc.x); acc.y = fmaf(xv3.y, ev3.y, acc.y);
            acc.z = fmaf(xv3.z, ev3.z, acc.z); acc.w = fmaf(xv3.w, ev3.w, acc.w);
        }
        for (; j < take; j++) {
            int e = __shfl_sync(0xFFFFFFFFu, p.x, j);
            int s = __shfl_sync(0xFFFFFFFFu, p.y, j);
            float4 ev = ldcs4(reinterpret_cast<const float4*>(ea + (long long)e * DIN) + lane);
            float4 xv = reinterpret_cast<const float4*>(x + (long long)s * DIN)[lane];
            acc.x = fmaf(xv.x, ev.x, acc.x);
            acc.y = fmaf(xv.y, ev.y, acc.y);
            acc.z = fmaf(xv.z, ev.z, acc.z);
            acc.w = fmaf(xv.w, ev.w, acc.w);
        }
    }
    int deg = end - beg;
    float inv = (deg > 0) ? (1.0f / (float)deg) : 0.f;
    acc.x *= inv; acc.y *= inv; acc.z *= inv; acc.w *= inv;
    reinterpret_cast<float4*>(agg0 + (long long)warp * DIN)[lane] = acc;
}

// ---------------- xpart: xp = x @ W0_top + b0 (runs on side stream) ----------------
__global__ void xpart_kernel(const float* __restrict__ x,
                             const float* __restrict__ W0,
                             const float* __restrict__ b0,
                             float* __restrict__ xp,
                             int N)
{
    __shared__ float sW[64 * HID];
    __shared__ float sF[64 * 64];

    int tid = threadIdx.x;
    int to = tid & 15;
    int tn = tid >> 4;
    int base = blockIdx.x * 64;

    float4 bias = reinterpret_cast<const float4*>(b0)[to];
    float c[4][4];
    #pragma unroll
    for (int i = 0; i < 4; i++) {
        c[i][0] = bias.x; c[i][1] = bias.y; c[i][2] = bias.z; c[i][3] = bias.w;
    }

    for (int kc = 0; kc < 2; kc++) {
        {
            const float4* w4 = reinterpret_cast<const float4*>(W0 + kc * 64 * HID);
            float4* sw4 = reinterpret_cast<float4*>(sW);
            #pragma unroll
            for (int i = 0; i < 4; i++) sw4[tid + 256 * i] = w4[tid + 256 * i];
        }
        {
            int koff4 = kc * 16;
            for (int i = tid; i < 64 * 16; i += 256) {
                int ln = i >> 4;
                int kq = i & 15;
                int node = base + ln;
                float4 v = make_float4(0.f, 0.f, 0.f, 0.f);
                if (node < N)
                    v = reinterpret_cast<const float4*>(x + (long long)node * DIN)[koff4 + kq];
                reinterpret_cast<float4*>(sF + ln * 64)[kq] = v;
            }
        }
        __syncthreads();

        const float* fa0 = sF + (4 * tn + 0) * 64;
        const float* fa1 = sF + (4 * tn + 1) * 64;
        const float* fa2 = sF + (4 * tn + 2) * 64;
        const float* fa3 = sF + (4 * tn + 3) * 64;

        #pragma unroll 8
        for (int k = 0; k < 64; k++) {
            float4 b = reinterpret_cast<const float4*>(sW + k * HID)[to];
            float a0 = fa0[k], a1 = fa1[k], a2 = fa2[k], a3 = fa3[k];
            c[0][0] = fmaf(a0, b.x, c[0][0]); c[0][1] = fmaf(a0, b.y, c[0][1]);
            c[0][2] = fmaf(a0, b.z, c[0][2]); c[0][3] = fmaf(a0, b.w, c[0][3]);
            c[1][0] = fmaf(a1, b.x, c[1][0]); c[1][1] = fmaf(a1, b.y, c[1][1]);
            c[1][2] = fmaf(a1, b.z, c[1][2]); c[1][3] = fmaf(a1, b.w, c[1][3]);
            c[2][0] = fmaf(a2, b.x, c[2][0]); c[2][1] = fmaf(a2, b.y, c[2][1]);
            c[2][2] = fmaf(a2, b.z, c[2][2]); c[2][3] = fmaf(a2, b.w, c[2][3]);
            c[3][0] = fmaf(a3, b.x, c[3][0]); c[3][1] = fmaf(a3, b.y, c[3][1]);
            c[3][2] = fmaf(a3, b.z, c[3][2]); c[3][3] = fmaf(a3, b.w, c[3][3]);
        }
        __syncthreads();
    }

    #pragma unroll
    for (int i = 0; i < 4; i++) {
        int node = base + 4 * tn + i;
        if (node < N) {
            float4 o = make_float4(c[i][0], c[i][1], c[i][2], c[i][3]);
            reinterpret_cast<float4*>(xp + (long long)node * HID)[to] = o;
        }
    }
}

// ---------------- combine: h = relu(xp + agg0 @ W0_bot) ----------------
__global__ void combine_kernel(const float* __restrict__ agg0,
                               const float* __restrict__ xp,
                               const float* __restrict__ W0,
                               float* __restrict__ h,
                               int N)
{
    __shared__ float sW[64 * HID];
    __shared__ float sF[64 * 64];

    int tid = threadIdx.x;
    int to = tid & 15;
    int tn = tid >> 4;
    int base = blockIdx.x * 64;

    float c[4][4];
    #pragma unroll
    for (int i = 0; i < 4; i++) {
        int node = base + 4 * tn + i;
        float4 p = make_float4(0.f, 0.f, 0.f, 0.f);
        if (node < N) p = reinterpret_cast<const float4*>(xp + (long long)node * HID)[to];
        c[i][0] = p.x; c[i][1] = p.y; c[i][2] = p.z; c[i][3] = p.w;
    }

    for (int kc = 0; kc < 2; kc++) {
        {
            const float4* w4 = reinterpret_cast<const float4*>(W0 + (2 + kc) * 64 * HID);
            float4* sw4 = reinterpret_cast<float4*>(sW);
            #pragma unroll
            for (int i = 0; i < 4; i++) sw4[tid + 256 * i] = w4[tid + 256 * i];
        }
        {
            int koff4 = kc * 16;
            for (int i = tid; i < 64 * 16; i += 256) {
                int ln = i >> 4;
                int kq = i & 15;
                int node = base + ln;
                float4 v = make_float4(0.f, 0.f, 0.f, 0.f);
                if (node < N)
                    v = reinterpret_cast<const float4*>(agg0 + (long long)node * DIN)[koff4 + kq];
                reinterpret_cast<float4*>(sF + ln * 64)[kq] = v;
            }
        }
        __syncthreads();

        const float* fa0 = sF + (4 * tn + 0) * 64;
        const float* fa1 = sF + (4 * tn + 1) * 64;
        const float* fa2 = sF + (4 * tn + 2) * 64;
        const float* fa3 = sF + (4 * tn + 3) * 64;

        #pragma unroll 8
        for (int k = 0; k < 64; k++) {
            float4 b = reinterpret_cast<const float4*>(sW + k * HID)[to];
            float a0 = fa0[k], a1 = fa1[k], a2 = fa2[k], a3 = fa3[k];
            c[0][0] = fmaf(a0, b.x, c[0][0]); c[0][1] = fmaf(a0, b.y, c[0][1]);
            c[0][2] = fmaf(a0, b.z, c[0][2]); c[0][3] = fmaf(a0, b.w, c[0][3]);
            c[1][0] = fmaf(a1, b.x, c[1][0]); c[1][1] = fmaf(a1, b.y, c[1][1]);
            c[1][2] = fmaf(a1, b.z, c[1][2]); c[1][3] = fmaf(a1, b.w, c[1][3]);
            c[2][0] = fmaf(a2, b.x, c[2][0]); c[2][1] = fmaf(a2, b.y, c[2][1]);
            c[2][2] = fmaf(a2, b.z, c[2][2]); c[2][3] = fmaf(a2, b.w, c[2][3]);
            c[3][0] = fmaf(a3, b.x, c[3][0]); c[3][1] = fmaf(a3, b.y, c[3][1]);
            c[3][2] = fmaf(a3, b.z, c[3][2]); c[3][3] = fmaf(a3, b.w, c[3][3]);
        }
        __syncthreads();
    }

    #pragma unroll
    for (int i = 0; i < 4; i++) {
        int node = base + 4 * tn + i;
        if (node < N) {
            float4 o;
            o.x = fmaxf(c[i][0], 0.f);
            o.y = fmaxf(c[i][1], 0.f);
            o.z = fmaxf(c[i][2], 0.f);
            o.w = fmaxf(c[i][3], 0.f);
            reinterpret_cast<float4*>(h + (long long)node * HID)[to] = o;
        }
    }
}

// ---------------- fused layer 1: half-warp float4, padded batches ----------------
__global__ void __launch_bounds__(256, 6)
agg1_fused_kernel(const float* __restrict__ h,
                  const float* __restrict__ ea,
                  const int2* __restrict__ perm,
                  const int* __restrict__ rowstart,
                  const float* __restrict__ W1,
                  const float* __restrict__ b1,
                  float* __restrict__ out,
                  int N)
{
    __shared__ float swB[2 * HID];
    __shared__ float swT[2 * HID];
    __shared__ float sb[DOUT];
    if (threadIdx.x < 2 * HID) {
        swT[threadIdx.x] = W1[threadIdx.x];
        swB[threadIdx.x] = W1[2 * HID + threadIdx.x];
    }
    if (threadIdx.x < DOUT) sb[threadIdx.x] = b1[threadIdx.x];
    __syncthreads();

    int warp = (blockIdx.x * blockDim.x + threadIdx.x) >> 5;
    int lane = threadIdx.x & 31;
    int half = lane >> 4;
    int sub  = lane & 15;
    if (warp >= N) return;

    int beg = rowstart[warp];
    int end = rowstart[warp + 1];

    float4 acc = make_float4(0.f, 0.f, 0.f, 0.f);
    for (int base = beg; base < end; base += 32) {
        int take = min(end - base, 32);
        int2 p = make_int2(0, 0);
        if (lane < take) p = perm[base + lane];

        for (int j = 0; j < take; j += 8) {
            int i0 = j + 4 * half;
            int tk1 = take - 1;
            int si0 = min(i0 + 0, tk1), si1 = min(i0 + 1, tk1);
            int si2 = min(i0 + 2, tk1), si3 = min(i0 + 3, tk1);
            bool v0 = (i0 + 0) < take, v1 = (i0 + 1) < take;
            bool v2 = (i0 + 2) < take, v3 = (i0 + 3) < take;

            int e0 = __shfl_sync(0xFFFFFFFFu, p.x, si0);
            int s0 = __shfl_sync(0xFFFFFFFFu, p.y, si0);
            int e1 = __shfl_sync(0xFFFFFFFFu, p.x, si1);
            int s1 = __shfl_sync(0xFFFFFFFFu, p.y, si1);
            int e2 = __shfl_sync(0xFFFFFFFFu, p.x, si2);
            int s2 = __shfl_sync(0xFFFFFFFFu, p.y, si2);
            int e3 = __shfl_sync(0xFFFFFFFFu, p.x, si3);
            int s3 = __shfl_sync(0xFFFFFFFFu, p.y, si3);

            float4 ev0 = ldcs4(reinterpret_cast<const float4*>(ea + (long long)e0 * HID) + sub);
            float4 ev1 = ldcs4(reinterpret_cast<const float4*>(ea + (long long)e1 * HID) + sub);
            float4 ev2 = ldcs4(reinterpret_cast<const float4*>(ea + (long long)e2 * HID) + sub);
            float4 ev3 = ldcs4(reinterpret_cast<const float4*>(ea + (long long)e3 * HID) + sub);
            float4 hv0 = reinterpret_cast<const float4*>(h + (long long)s0 * HID)[sub];
            float4 hv1 = reinterpret_cast<const float4*>(h + (long long)s1 * HID)[sub];
            float4 hv2 = reinterpret_cast<const float4*>(h + (long long)s2 * HID)[sub];
            float4 hv3 = reinterpret_cast<const float4*>(h + (long long)s3 * HID)[sub];

            if (!v0) hv0 = make_float4(0.f, 0.f, 0.f, 0.f);
            if (!v1) hv1 = make_float4(0.f, 0.f, 0.f, 0.f);
            if (!v2) hv2 = make_float4(0.f, 0.f, 0.f, 0.f);
            if (!v3) hv3 = make_float4(0.f, 0.f, 0.f, 0.f);

            acc.x = fmaf(hv0.x, ev0.x, acc.x); acc.y = fmaf(hv0.y, ev0.y, acc.y);
            acc.z = fmaf(hv0.z, ev0.z, acc.z); acc.w = fmaf(hv0.w, ev0.w, acc.w);
            acc.x = fmaf(hv1.x, ev1.x, acc.x); acc.y = fmaf(hv1.y, ev1.y, acc.y);
            acc.z = fmaf(hv1.z, ev1.z, acc.z); acc.w = fmaf(hv1.w, ev1.w, acc.w);
            acc.x = fmaf(hv2.x, ev2.x, acc.x); acc.y = fmaf(hv2.y, ev2.y, acc.y);
            acc.z = fmaf(hv2.z, ev2.z, acc.z); acc.w = fmaf(hv2.w, ev2.w, acc.w);
            acc.x = fmaf(hv3.x, ev3.x, acc.x); acc.y = fmaf(hv3.y, ev3.y, acc.y);
            acc.z = fmaf(hv3.z, ev3.z, acc.z); acc.w = fmaf(hv3.w, ev3.w, acc.w);
        }
    }

    acc.x += __shfl_xor_sync(0xFFFFFFFFu, acc.x, 16);
    acc.y += __shfl_xor_sync(0xFFFFFFFFu, acc.y, 16);
    acc.z += __shfl_xor_sync(0xFFFFFFFFu, acc.z, 16);
    acc.w += __shfl_xor_sync(0xFFFFFFFFu, acc.w, 16);

    int deg = end - beg;
    float inv = (deg > 0) ? (1.0f / (float)deg) : 0.f;

    float4 hd = reinterpret_cast<const float4*>(h + (long long)warp * HID)[sub];

    int c0 = 4 * sub;
    float r0 = inv * (acc.x * swB[(c0 + 0) * 2 + 0] + acc.y * swB[(c0 + 1) * 2 + 0]
                    + acc.z * swB[(c0 + 2) * 2 + 0] + acc.w * swB[(c0 + 3) * 2 + 0])
             +        hd.x * swT[(c0 + 0) * 2 + 0] + hd.y * swT[(c0 + 1) * 2 + 0]
             +        hd.z * swT[(c0 + 2) * 2 + 0] + hd.w * swT[(c0 + 3) * 2 + 0];
    float r1 = inv * (acc.x * swB[(c0 + 0) * 2 + 1] + acc.y * swB[(c0 + 1) * 2 + 1]
                    + acc.z * swB[(c0 + 2) * 2 + 1] + acc.w * swB[(c0 + 3) * 2 + 1])
             +        hd.x * swT[(c0 + 0) * 2 + 1] + hd.y * swT[(c0 + 1) * 2 + 1]
             +        hd.z * swT[(c0 + 2) * 2 + 1] + hd.w * swT[(c0 + 3) * 2 + 1];

    #pragma unroll
    for (int o = 8; o > 0; o >>= 1) {
        r0 += __shfl_xor_sync(0xFFFFFFFFu, r0, o);
        r1 += __shfl_xor_sync(0xFFFFFFFFu, r1, o);
    }
    if (lane == 0) {
        out[(long long)warp * DOUT + 0] = r0 + sb[0];
        out[(long long)warp * DOUT + 1] = r1 + sb[1];
    }
}

// ---------------------------------------------------------------------------
extern "C" void kernel_launch(void* const* d_in, const int* in_sizes, int n_in,
                              void* d_out, int out_size)
{
    const float* x   = (const float*)d_in[0];
    const int*   ei  = (const int*)d_in[1];
    const float* ea0 = (const float*)d_in[2];
    const float* ea1 = (const float*)d_in[3];
    const float* W0  = (const float*)d_in[4];
    const float* b0  = (const float*)d_in[5];
    const float* W1  = (const float*)d_in[6];
    const float* b1  = (const float*)d_in[7];
    float* out = (float*)d_out;

    const int N = in_sizes[0] / DIN;
    const int E = in_sizes[1] / 2;

    int *hist_p, *rowstart_p, *cursor_p;
    int2 *perm_p;
    float *agg0_p, *xpart_p, *h_p;
    cudaGetSymbolAddress((void**)&hist_p,     g_hist);
    cudaGetSymbolAddress((void**)&rowstart_p, g_rowstart);
    cudaGetSymbolAddress((void**)&cursor_p,   g_cursor);
    cudaGetSymbolAddress((void**)&perm_p,     g_perm);
    cudaGetSymbolAddress((void**)&agg0_p,     g_agg0);
    cudaGetSymbolAddress((void**)&xpart_p,    g_xpart);
    cudaGetSymbolAddress((void**)&h_p,        g_h);

    // side stream + fork/join events (host-side objects only; no device memory)
    cudaStream_t s2;
    cudaEvent_t evA, evB;
    cudaStreamCreateWithFlags(&s2, cudaStreamNonBlocking);
    cudaEventCreateWithFlags(&evA, cudaEventDisableTiming);
    cudaEventCreateWithFlags(&evB, cudaEventDisableTiming);

    // fork: xpart (x @ W0_top + b0) runs concurrently with binning + agg0
    cudaEventRecord(evA, 0);
    cudaStreamWaitEvent(s2, evA, 0);
    xpart_kernel<<<(N + 63) / 64, 256, 0, s2>>>(x, W0, b0, xpart_p, N);
    cudaEventRecord(evB, s2);

    // main stream: binning chain + layer-0 aggregation
    {
        int quads = (E + 3) / 4;
        hist_kernel<<<(quads + 255) / 256, 256>>>(ei, hist_p, E);
        scan_kernel<<<1, 1024>>>(hist_p, rowstart_p, cursor_p, N, E);
        build_kernel<<<(quads + 255) / 256, 256>>>(ei, cursor_p, perm_p, E);
    }
    agg0_kernel<<<(N * 32 + 255) / 256, 256>>>(x, ea0, perm_p, rowstart_p, agg0_p, N);

    // join: combine needs xpart
    cudaStreamWaitEvent(0, evB, 0);
    combine_kernel<<<(N + 63) / 64, 256>>>(agg0_p, xpart_p, W0, h_p, N);

    // fused layer-1
    agg1_fused_kernel<<<(N * 32 + 255) / 256, 256>>>(h_p, ea1, perm_p, rowstart_p,
                                                     W1, b1, out, N);
}